// round 14
// baseline (speedup 1.0000x reference)
#include <cuda_runtime.h>
#include <cuda_bf16.h>
#include <cstdint>
#include <stdint.h>
#include <math.h>

// Problem constants
#define BSZ   8
#define NTOK  4096
#define DDIM  256
#define QKD   128
#define MSL   32
#define MSEG  8      // K-token segments for the lse kernel (512 K rows each)
#define OSEG  32     // n-range segments for the output kernel

#define SCLOG2E (0.08838834764831845f * 1.44269504088896340f)  // scale * log2(e)
#define LOG2E   1.44269504088896340f

// ---------------- scratch (static device globals; no allocs allowed) ----------
__device__ __align__(16) __nv_bfloat16 g_Hb[BSZ * NTOK * DDIM];
__device__ __align__(16) __nv_bfloat16 g_Xb[BSZ * NTOK * DDIM];
__device__ __align__(16) __nv_bfloat16 g_Wqb[QKD * DDIM];   // [q][d] (transposed)
__device__ __align__(16) __nv_bfloat16 g_Wkb[QKD * DDIM];
__device__ __align__(16) __nv_bfloat16 g_Qh[BSZ * NTOK * QKD];
__device__ __align__(16) __nv_bfloat16 g_Kh[BSZ * NTOK * QKD];
__device__ float g_plse[BSZ * NTOK * MSEG];
__device__ float g_wkeep[BSZ * NTOK];
__device__ float g_slotw[MSL * NTOK];
__device__ float g_den[BSZ * MSL];
__device__ float g_pout[BSZ * OSEG * MSL * DDIM];

// ---------------- PTX helpers (baseline sm_100) ----------------
__device__ __forceinline__ uint32_t smem_u32(const void* p) {
    uint32_t a;
    asm("{ .reg .u64 t; cvta.to.shared.u64 t, %1; cvt.u32.u64 %0, t; }" : "=r"(a) : "l"(p));
    return a;
}
__device__ __forceinline__ void cp16(uint32_t dst, const void* src) {
    asm volatile("cp.async.cg.shared.global [%0], [%1], 16;" :: "r"(dst), "l"(src) : "memory");
}
#define CP_COMMIT() asm volatile("cp.async.commit_group;" ::: "memory")
#define CP_WAIT0()  asm volatile("cp.async.wait_group 0;" ::: "memory")
#define CP_WAIT1()  asm volatile("cp.async.wait_group 1;" ::: "memory")

__device__ __forceinline__ void ldsm4(uint32_t* r, uint32_t addr) {
    asm volatile("ldmatrix.sync.aligned.m8n8.x4.shared.b16 {%0,%1,%2,%3}, [%4];"
                 : "=r"((r)[0]), "=r"((r)[1]), "=r"((r)[2]), "=r"((r)[3]) : "r"(addr));
}
__device__ __forceinline__ void mma16816(float* c, const uint32_t* a, const uint32_t* b) {
    asm volatile(
        "mma.sync.aligned.m16n8k16.row.col.f32.bf16.bf16.f32 "
        "{%0,%1,%2,%3}, {%4,%5,%6,%7}, {%8,%9}, {%0,%1,%2,%3};"
        : "+f"((c)[0]), "+f"((c)[1]), "+f"((c)[2]), "+f"((c)[3])
        : "r"((a)[0]), "r"((a)[1]), "r"((a)[2]), "r"((a)[3]),
          "r"((b)[0]), "r"((b)[1]));
}
__device__ __forceinline__ float ex2f(float x) {
    float y;
    asm("ex2.approx.f32 %0, %1;" : "=f"(y) : "f"(x));
    return y;
}
__device__ __forceinline__ uint32_t packbf2(float a, float b) {
    __nv_bfloat162 p = __halves2bfloat162(__float2bfloat16(a), __float2bfloat16(b));
    return *reinterpret_cast<uint32_t*>(&p);
}

// ============================================================================
// convert inputs + weights to bf16 (merged; blocks 0..8191 inputs, rest weights)
// ============================================================================
__global__ void convert_kernel(const float* __restrict__ X0, const float* __restrict__ H0,
                               const float* __restrict__ Wq, const float* __restrict__ Wk) {
    if (blockIdx.x < 8192) {
        const size_t i = (size_t)blockIdx.x * 256 + threadIdx.x;   // float4 index
        float4 h = reinterpret_cast<const float4*>(H0)[i];
        float4 x = reinterpret_cast<const float4*>(X0)[i];
        reinterpret_cast<uint2*>(g_Hb)[i] = make_uint2(packbf2(h.x, h.y), packbf2(h.z, h.w));
        reinterpret_cast<uint2*>(g_Xb)[i] = make_uint2(packbf2(x.x, x.y), packbf2(x.z, x.w));
    } else {
        const int i = (blockIdx.x - 8192) * 256 + threadIdx.x;  // over QKD*DDIM
        const int q = i >> 8, d = i & 255;
        g_Wqb[i] = __float2bfloat16(Wq[d * QKD + q]);
        g_Wkb[i] = __float2bfloat16(Wk[d * QKD + q]);
    }
}

// ============================================================================
// proj via mma: Q = Hb @ Wqb^T, K = Xb @ Wkb^T.  M=128/block, N=128, K=256.
// grid (256 rowtiles, 2), 256 thr (8 warps x 16 rows).
// K split into 2 col-halves, double-buffered via cp.async groups.
// ============================================================================
#define PJW 528                        // 256 bf16 cols padded (264 elems)
#define PJ_IN   (128 * PJW)            // 67584
#define PJ_SMEM (2 * PJ_IN)            // 135168

__global__ __launch_bounds__(256, 1)
void proj_mma_kernel() {
    extern __shared__ __align__(16) char dsm[];
    const uint32_t base = smem_u32(dsm);
    const int which = blockIdx.y;
    const __nv_bfloat16* __restrict__ In = which ? g_Xb : g_Hb;
    const __nv_bfloat16* __restrict__ Wt = which ? g_Wkb : g_Wqb;
    __nv_bfloat16* __restrict__ Out = which ? g_Kh : g_Qh;

    const int r0  = blockIdx.x * 128;
    const int tid = threadIdx.x;
    const int wid = tid >> 5;
    const int l   = tid & 31;

    // group 1: cols 0..127 of In (128 rows) + Wt (128 rows)
    for (int idx = tid; idx < 2048; idx += 256) {
        const int r = idx >> 4, c = idx & 15;
        cp16(base + (uint32_t)r * PJW + (uint32_t)c * 16,
             In + (size_t)(r0 + r) * DDIM + c * 8);
        cp16(base + PJ_IN + (uint32_t)r * PJW + (uint32_t)c * 16,
             Wt + (size_t)r * DDIM + c * 8);
    }
    CP_COMMIT();
    // group 2: cols 128..255
    for (int idx = tid; idx < 2048; idx += 256) {
        const int r = idx >> 4, c = idx & 15;
        cp16(base + (uint32_t)r * PJW + 256 + (uint32_t)c * 16,
             In + (size_t)(r0 + r) * DDIM + 128 + c * 8);
        cp16(base + PJ_IN + (uint32_t)r * PJW + 256 + (uint32_t)c * 16,
             Wt + (size_t)r * DDIM + 128 + c * 8);
    }
    CP_COMMIT();

    const uint32_t a_row = (uint32_t)(wid * 16 + (l & 7) + ((l >> 3) & 1) * 8);
    const uint32_t a_off = a_row * PJW + ((uint32_t)(l >> 4) & 1) * 16;
    const uint32_t b_row = (uint32_t)((l & 7) + ((l >> 4) & 1) * 8);
    const uint32_t b_off = b_row * PJW + (((uint32_t)(l >> 3)) & 1) * 16;

    float acc[64];
    #pragma unroll
    for (int i = 0; i < 64; ++i) acc[i] = 0.f;

    CP_WAIT1();
    __syncthreads();
    #pragma unroll
    for (int kc = 0; kc < 8; ++kc) {
        uint32_t a[4];
        ldsm4(a, base + a_off + kc * 32);
        #pragma unroll
        for (int p = 0; p < 8; ++p) {
            uint32_t bb[4];
            ldsm4(bb, base + PJ_IN + (uint32_t)p * (16 * PJW) + b_off + kc * 32);
            mma16816(acc + (2 * p) * 4,     a, bb + 0);
            mma16816(acc + (2 * p + 1) * 4, a, bb + 2);
        }
    }
    CP_WAIT0();
    __syncthreads();
    #pragma unroll
    for (int kc = 8; kc < 16; ++kc) {
        uint32_t a[4];
        ldsm4(a, base + a_off + kc * 32);
        #pragma unroll
        for (int p = 0; p < 8; ++p) {
            uint32_t bb[4];
            ldsm4(bb, base + PJ_IN + (uint32_t)p * (16 * PJW) + b_off + kc * 32);
            mma16816(acc + (2 * p) * 4,     a, bb + 0);
            mma16816(acc + (2 * p + 1) * 4, a, bb + 2);
        }
    }

    // store (R9-validated mapping): group g covers cols g*8..+7
    const int rr = r0 + wid * 16 + (l >> 2);
    #pragma unroll
    for (int g = 0; g < 16; ++g) {
        const int col = g * 8 + (l & 3) * 2;
        *reinterpret_cast<uint32_t*>(&Out[(size_t)rr * QKD + col]) =
            packbf2(acc[g * 4 + 0], acc[g * 4 + 1]);
        *reinterpret_cast<uint32_t*>(&Out[(size_t)(rr + 8) * QKD + col]) =
            packbf2(acc[g * 4 + 2], acc[g * 4 + 3]);
    }
}

// ============================================================================
// lse: bf16 mma S=QK^T -> per-row partial sum of exp.
// grid (32 ntiles, 8 b, MSEG=8), 256 thr (8 warps x 16 Q-rows).
// M=128/CTA -> 102KB smem, __launch_bounds__(256,2) -> 2 CTAs/SM, 4 warps/SMSP.
// A-fragments hoisted once; per-p fold; K double-buffered.
// ============================================================================
#define PDW 272
#define KTB (128 * PDW)                // 34816
#define QSZ (128 * PDW)                // 34816
#define SMEM_LSE (QSZ + 2 * KTB)       // 104448  (x2 CTAs = 208896 < 227KB)

__global__ __launch_bounds__(256, 2)
void lse_mma_kernel() {
    extern __shared__ __align__(16) char dsm[];
    const uint32_t base = smem_u32(dsm);

    const int b   = blockIdx.y;
    const int seg = blockIdx.z;
    const int n0  = blockIdx.x * 128;
    const int tid = threadIdx.x;
    const int wid = tid >> 5;
    const int l   = tid & 31;

    const __nv_bfloat16* __restrict__ Qh = g_Qh + ((size_t)b * NTOK + n0) * QKD;
    const __nv_bfloat16* __restrict__ Kh = g_Kh + (size_t)b * NTOK * QKD;

    // prologue: Q (128 rows) + K tile 0
    for (int idx = tid; idx < 2048; idx += 256) {
        const int r = idx >> 4, c = idx & 15;
        cp16(base + (uint32_t)r * PDW + (uint32_t)c * 16, Qh + (size_t)r * QKD + c * 8);
        cp16(base + QSZ + (uint32_t)r * PDW + (uint32_t)c * 16,
             Kh + ((size_t)(seg * 512 + r)) * QKD + c * 8);
    }
    CP_COMMIT();
    CP_WAIT0();
    __syncthreads();

    const uint32_t a_row = (uint32_t)(wid * 16 + (l & 7) + ((l >> 3) & 1) * 8);
    const uint32_t a_off = a_row * PDW + ((uint32_t)(l >> 4) & 1) * 16;
    const uint32_t b_row = (uint32_t)((l & 7) + ((l >> 4) & 1) * 8);
    const uint32_t b_off = b_row * PDW + (((uint32_t)(l >> 3)) & 1) * 16;

    // hoist A fragments for the whole kernel (Q smem never rewritten): 32 regs
    uint32_t af[8][4];
    #pragma unroll
    for (int kc = 0; kc < 8; ++kc)
        ldsm4(af[kc], base + a_off + kc * 32);

    float rs0 = 0.f, rs1 = 0.f;

    for (int mt = 0; mt < 4; ++mt) {
        const int sb = mt & 1;
        if (mt + 1 < 4) {
            const int m0 = seg * 512 + (mt + 1) * 128;
            const uint32_t kb = base + QSZ + ((mt + 1) & 1) * KTB;
            for (int idx = tid; idx < 2048; idx += 256) {
                const int r = idx >> 4, c = idx & 15;
                cp16(kb + (uint32_t)r * PDW + (uint32_t)c * 16,
                     Kh + ((size_t)(m0 + r)) * QKD + c * 8);
            }
            CP_COMMIT();
            CP_WAIT1();
        } else {
            CP_WAIT0();
        }
        __syncthreads();

        const uint32_t kh = base + QSZ + (uint32_t)sb * KTB;

        #pragma unroll
        for (int p = 0; p < 8; ++p) {
            float acc[8];
            #pragma unroll
            for (int i = 0; i < 8; ++i) acc[i] = 0.f;
            #pragma unroll
            for (int kc = 0; kc < 8; ++kc) {
                uint32_t bh[4];
                ldsm4(bh, kh + (uint32_t)p * (16 * PDW) + b_off + kc * 32);
                mma16816(acc + 0, af[kc], bh + 0);
                mma16816(acc + 4, af[kc], bh + 2);
            }
            rs0 += ex2f(acc[0] * SCLOG2E) + ex2f(acc[1] * SCLOG2E)
                 + ex2f(acc[4] * SCLOG2E) + ex2f(acc[5] * SCLOG2E);
            rs1 += ex2f(acc[2] * SCLOG2E) + ex2f(acc[3] * SCLOG2E)
                 + ex2f(acc[6] * SCLOG2E) + ex2f(acc[7] * SCLOG2E);
        }
        __syncthreads();
    }

    rs0 += __shfl_xor_sync(0xFFFFFFFFu, rs0, 1);
    rs0 += __shfl_xor_sync(0xFFFFFFFFu, rs0, 2);
    rs1 += __shfl_xor_sync(0xFFFFFFFFu, rs1, 1);
    rs1 += __shfl_xor_sync(0xFFFFFFFFu, rs1, 2);
    if ((l & 3) == 0) {
        const int row = n0 + wid * 16 + (l >> 2);
        g_plse[(size_t)(b * NTOK + row) * MSEG + seg]     = rs0;
        g_plse[(size_t)(b * NTOK + row + 8) * MSEG + seg] = rs1;
    }
}

// ============================================================================
// merged: blocks 0..7 -> w_keep = s/sum(s); blocks 8..39 -> slot softmax
// ============================================================================
__global__ void wk_slots_kernel(const float* __restrict__ slot_logits) {
    __shared__ float vals[NTOK];
    __shared__ float sred[256];
    const int tid = threadIdx.x;

    if (blockIdx.x < BSZ) {
        const int b = blockIdx.x;
        float sv[16];
        float loc = 0.f;
        #pragma unroll
        for (int j = 0; j < 16; ++j) {
            const int n = j * 256 + tid;
            const float* p = &g_plse[(size_t)(b * NTOK + n) * MSEG];
            float s = 0.f;
            #pragma unroll
            for (int k = 0; k < MSEG; ++k) s += p[k];
            sv[j] = s;
            loc += s;
        }
        sred[tid] = loc; __syncthreads();
        for (int st = 128; st; st >>= 1) {
            if (tid < st) sred[tid] += sred[tid + st];
            __syncthreads();
        }
        const float inv = 1.f / sred[0];
        #pragma unroll
        for (int j = 0; j < 16; ++j)
            g_wkeep[(size_t)b * NTOK + j * 256 + tid] = sv[j] * inv;
    } else {
        const int row = blockIdx.x - BSZ;
        const float* __restrict__ x = slot_logits + (size_t)row * NTOK;
        float* __restrict__ y = g_slotw + (size_t)row * NTOK;
        float sm = 0.f;
        for (int i = tid; i < NTOK; i += 256) {
            const float e = ex2f(x[i] * LOG2E);
            vals[i] = e;
            sm += e;
        }
        sred[tid] = sm; __syncthreads();
        for (int s = 128; s; s >>= 1) {
            if (tid < s) sred[tid] += sred[tid + s];
            __syncthreads();
        }
        const float inv = 1.f / sred[0];
        for (int i = tid; i < NTOK; i += 256) y[i] = vals[i] * inv;
    }
}

// den[b][m] = sum_n slot_w[m][n] * w_keep[b][n]
__global__ void den_kernel() {
    const int m = blockIdx.x, b = blockIdx.y;
    __shared__ float sred[256];
    const int tid = threadIdx.x;
    const float* __restrict__ sw = g_slotw + (size_t)m * NTOK;
    const float* __restrict__ wk = g_wkeep + (size_t)b * NTOK;
    float s = 0.f;
    for (int n = tid; n < NTOK; n += 256) s = fmaf(sw[n], wk[n], s);
    sred[tid] = s; __syncthreads();
    for (int st = 128; st; st >>= 1) {
        if (tid < st) sred[tid] += sred[tid + st];
        __syncthreads();
    }
    if (tid == 0) g_den[b * MSL + m] = sred[0];
}

// ============================================================================
// partial out over n-segments, fp32 H0 (bf16 H costs 1.6e-3 rel err — output
// is a near-uniform average, bf16 noise does NOT wash out).
// grid (8 b, 16), 256 thr: half h = tid>>7 handles 128 n, col = tid&127.
// ============================================================================
__global__ __launch_bounds__(256, 1)
void pout_kernel(const float* __restrict__ H0) {
    const int b = blockIdx.x, sege = blockIdx.y;
    const int tid = threadIdx.x;
    const int h   = tid >> 7;         // 0/1: n-half
    const int col = tid & 127;        // d pair (d = 2*col)
    __shared__ float csh[MSL][256];

    const int nb = sege * 256;
    for (int i = tid; i < MSL * 256; i += 256) {
        const int m = i >> 8, nn = i & 255;
        csh[m][nn] = g_slotw[(size_t)m * NTOK + nb + nn]
                   * g_wkeep[(size_t)b * NTOK + nb + nn];
    }
    __syncthreads();

    float acc0[MSL], acc1[MSL];
    #pragma unroll
    for (int m = 0; m < MSL; ++m) { acc0[m] = 0.f; acc1[m] = 0.f; }

    const int n0 = nb + h * 128;
    for (int nn = 0; nn < 128; ++nn) {
        const float2 h2 = *reinterpret_cast<const float2*>(
            &H0[((size_t)b * NTOK + n0 + nn) * DDIM + 2 * col]);
        #pragma unroll
        for (int m = 0; m < MSL; ++m) {
            const float w = csh[m][h * 128 + nn];
            acc0[m] = fmaf(w, h2.x, acc0[m]);
            acc1[m] = fmaf(w, h2.y, acc1[m]);
        }
    }
    const int seg = sege * 2 + h;
    #pragma unroll
    for (int m = 0; m < MSL; ++m) {
        float2 v = make_float2(acc0[m], acc1[m]);
        *reinterpret_cast<float2*>(
            &g_pout[((size_t)((b * OSEG + seg) * MSL) + m) * DDIM + 2 * col]) = v;
    }
}

// out = (sum_seg partial) / (den + 1e-6)
__global__ void final_kernel(float* __restrict__ out) {
    const int idx = blockIdx.x * 256 + threadIdx.x;
    if (idx >= BSZ * MSL * DDIM) return;
    const int m = (idx >> 8) & 31;
    const int b = idx >> 13;
    float s = 0.f;
    #pragma unroll
    for (int seg = 0; seg < OSEG; ++seg)
        s += g_pout[((size_t)((b * OSEG + seg) * MSL) + m) * DDIM + (idx & 255)];
    out[idx] = s / (g_den[b * MSL + m] + 1e-6f);
}

// ============================================================================
extern "C" void kernel_launch(void* const* d_in, const int* in_sizes, int n_in,
                              void* d_out, int out_size) {
    const float* X0  = (const float*)d_in[0];
    const float* H0  = (const float*)d_in[1];
    const float* Wq  = (const float*)d_in[2];
    const float* Wk  = (const float*)d_in[3];
    const float* slo = (const float*)d_in[4];
    float* out = (float*)d_out;

    cudaFuncSetAttribute(proj_mma_kernel, cudaFuncAttributeMaxDynamicSharedMemorySize, PJ_SMEM);
    cudaFuncSetAttribute(lse_mma_kernel,  cudaFuncAttributeMaxDynamicSharedMemorySize, SMEM_LSE);

    convert_kernel<<<8192 + 128, 256>>>(X0, H0, Wq, Wk);
    proj_mma_kernel<<<dim3(256, 2), 256, PJ_SMEM>>>();
    lse_mma_kernel<<<dim3(NTOK / 128, BSZ, MSEG), 256, SMEM_LSE>>>();
    wk_slots_kernel<<<BSZ + MSL, 256>>>(slo);
    den_kernel<<<dim3(MSL, BSZ), 256>>>();
    pout_kernel<<<dim3(BSZ, 16), 256>>>(H0);
    final_kernel<<<(BSZ * MSL * DDIM + 255) / 256, 256>>>(out);
}

// round 15
// speedup vs baseline: 1.1278x; 1.1278x over previous
#include <cuda_runtime.h>
#include <cuda_bf16.h>
#include <cuda_fp8.h>
#include <cstdint>
#include <stdint.h>
#include <math.h>

// Problem constants
#define BSZ   8
#define NTOK  4096
#define DDIM  256
#define QKD   128
#define MSL   32
#define MSEG  8      // K-token segments for the lse kernel (512 K rows each)
#define OSEG  64     // n-range segments for the output kernel (64 n each)

#define SCLOG2E (0.08838834764831845f * 1.44269504088896340f)  // scale * log2(e)
#define LOG2E   1.44269504088896340f

// ---------------- scratch (static device globals; no allocs allowed) ----------
__device__ __align__(16) __nv_bfloat16 g_Hb[BSZ * NTOK * DDIM];
__device__ __align__(16) __nv_bfloat16 g_Xb[BSZ * NTOK * DDIM];
__device__ __align__(16) __nv_bfloat16 g_Wqb[QKD * DDIM];   // [q][d] (transposed)
__device__ __align__(16) __nv_bfloat16 g_Wkb[QKD * DDIM];
__device__ __align__(16) uint8_t g_Qh8[BSZ * NTOK * QKD];   // e4m3
__device__ __align__(16) uint8_t g_Kh8[BSZ * NTOK * QKD];   // e4m3
__device__ float g_plse[BSZ * NTOK * MSEG];
__device__ float g_wkeep[BSZ * NTOK];
__device__ float g_slotw[MSL * NTOK];
__device__ float g_den[BSZ * MSL];
__device__ float g_pout[BSZ * OSEG * MSL * DDIM];

// ---------------- PTX helpers (baseline sm_100) ----------------
__device__ __forceinline__ uint32_t smem_u32(const void* p) {
    uint32_t a;
    asm("{ .reg .u64 t; cvta.to.shared.u64 t, %1; cvt.u32.u64 %0, t; }" : "=r"(a) : "l"(p));
    return a;
}
__device__ __forceinline__ void cp16(uint32_t dst, const void* src) {
    asm volatile("cp.async.cg.shared.global [%0], [%1], 16;" :: "r"(dst), "l"(src) : "memory");
}
#define CP_COMMIT() asm volatile("cp.async.commit_group;" ::: "memory")
#define CP_WAIT0()  asm volatile("cp.async.wait_group 0;" ::: "memory")
#define CP_WAIT1()  asm volatile("cp.async.wait_group 1;" ::: "memory")

__device__ __forceinline__ void ldsm4(uint32_t* r, uint32_t addr) {
    asm volatile("ldmatrix.sync.aligned.m8n8.x4.shared.b16 {%0,%1,%2,%3}, [%4];"
                 : "=r"((r)[0]), "=r"((r)[1]), "=r"((r)[2]), "=r"((r)[3]) : "r"(addr));
}
__device__ __forceinline__ void mma16816(float* c, const uint32_t* a, const uint32_t* b) {
    asm volatile(
        "mma.sync.aligned.m16n8k16.row.col.f32.bf16.bf16.f32 "
        "{%0,%1,%2,%3}, {%4,%5,%6,%7}, {%8,%9}, {%0,%1,%2,%3};"
        : "+f"((c)[0]), "+f"((c)[1]), "+f"((c)[2]), "+f"((c)[3])
        : "r"((a)[0]), "r"((a)[1]), "r"((a)[2]), "r"((a)[3]),
          "r"((b)[0]), "r"((b)[1]));
}
// fp8 e4m3 MMA, K=32 per instruction (2x MACs of the bf16 k16 form)
__device__ __forceinline__ void mma16832f8(float* c, const uint32_t* a, const uint32_t* b) {
    asm volatile(
        "mma.sync.aligned.m16n8k32.row.col.f32.e4m3.e4m3.f32 "
        "{%0,%1,%2,%3}, {%4,%5,%6,%7}, {%8,%9}, {%0,%1,%2,%3};"
        : "+f"((c)[0]), "+f"((c)[1]), "+f"((c)[2]), "+f"((c)[3])
        : "r"((a)[0]), "r"((a)[1]), "r"((a)[2]), "r"((a)[3]),
          "r"((b)[0]), "r"((b)[1]));
}
__device__ __forceinline__ float ex2f(float x) {
    float y;
    asm("ex2.approx.f32 %0, %1;" : "=f"(y) : "f"(x));
    return y;
}
__device__ __forceinline__ uint32_t packbf2(float a, float b) {
    __nv_bfloat162 p = __halves2bfloat162(__float2bfloat16(a), __float2bfloat16(b));
    return *reinterpret_cast<uint32_t*>(&p);
}
__device__ __forceinline__ unsigned short packfp8x2(float a, float b) {
    return (unsigned short)__nv_cvt_float2_to_fp8x2(make_float2(a, b), __NV_SATFINITE, __NV_E4M3);
}

// ============================================================================
// convert inputs + weights to bf16 (merged)
// ============================================================================
__global__ void convert_kernel(const float* __restrict__ X0, const float* __restrict__ H0,
                               const float* __restrict__ Wq, const float* __restrict__ Wk) {
    if (blockIdx.x < 8192) {
        const size_t i = (size_t)blockIdx.x * 256 + threadIdx.x;   // float4 index
        float4 h = reinterpret_cast<const float4*>(H0)[i];
        float4 x = reinterpret_cast<const float4*>(X0)[i];
        reinterpret_cast<uint2*>(g_Hb)[i] = make_uint2(packbf2(h.x, h.y), packbf2(h.z, h.w));
        reinterpret_cast<uint2*>(g_Xb)[i] = make_uint2(packbf2(x.x, x.y), packbf2(x.z, x.w));
    } else {
        const int i = (blockIdx.x - 8192) * 256 + threadIdx.x;  // over QKD*DDIM
        const int q = i >> 8, d = i & 255;
        g_Wqb[i] = __float2bfloat16(Wq[d * QKD + q]);
        g_Wkb[i] = __float2bfloat16(Wk[d * QKD + q]);
    }
}

// ============================================================================
// proj via bf16 mma (R12 shape: M=256/block, K-split pipeline), fp8 epilogue.
// grid (128 rowtiles, 2), 256 thr (8 warps x 32 rows).
// ============================================================================
#define PJW 528
#define PJ_IN   (256 * PJW)            // 135168
#define PJ_WT   (128 * PJW)            // 67584
#define PJ_SMEM (PJ_IN + PJ_WT)        // 202752

__global__ __launch_bounds__(256, 1)
void proj_mma_kernel() {
    extern __shared__ __align__(16) char dsm[];
    const uint32_t base = smem_u32(dsm);
    const int which = blockIdx.y;
    const __nv_bfloat16* __restrict__ In = which ? g_Xb : g_Hb;
    const __nv_bfloat16* __restrict__ Wt = which ? g_Wkb : g_Wqb;
    uint8_t* __restrict__ Out8 = which ? g_Kh8 : g_Qh8;

    const int r0  = blockIdx.x * 256;
    const int tid = threadIdx.x;
    const int wid = tid >> 5;
    const int l   = tid & 31;

    // group 1: cols 0..127
    for (int idx = tid; idx < 4096; idx += 256) {
        const int r = idx >> 4, c = idx & 15;
        cp16(base + (uint32_t)r * PJW + (uint32_t)c * 16,
             In + (size_t)(r0 + r) * DDIM + c * 8);
    }
    for (int idx = tid; idx < 2048; idx += 256) {
        const int r = idx >> 4, c = idx & 15;
        cp16(base + PJ_IN + (uint32_t)r * PJW + (uint32_t)c * 16,
             Wt + (size_t)r * DDIM + c * 8);
    }
    CP_COMMIT();
    // group 2: cols 128..255
    for (int idx = tid; idx < 4096; idx += 256) {
        const int r = idx >> 4, c = idx & 15;
        cp16(base + (uint32_t)r * PJW + 256 + (uint32_t)c * 16,
             In + (size_t)(r0 + r) * DDIM + 128 + c * 8);
    }
    for (int idx = tid; idx < 2048; idx += 256) {
        const int r = idx >> 4, c = idx & 15;
        cp16(base + PJ_IN + (uint32_t)r * PJW + 256 + (uint32_t)c * 16,
             Wt + (size_t)r * DDIM + 128 + c * 8);
    }
    CP_COMMIT();

    const uint32_t a_row = (uint32_t)(wid * 32 + (l & 7) + ((l >> 3) & 1) * 8);
    const uint32_t a_off = a_row * PJW + ((uint32_t)(l >> 4) & 1) * 16;
    const uint32_t b_row = (uint32_t)((l & 7) + ((l >> 4) & 1) * 8);
    const uint32_t b_off = b_row * PJW + (((uint32_t)(l >> 3)) & 1) * 16;

    float acc[8][2][8];
    #pragma unroll
    for (int p = 0; p < 8; ++p)
        #pragma unroll
        for (int af = 0; af < 2; ++af)
            #pragma unroll
            for (int i = 0; i < 8; ++i) acc[p][af][i] = 0.f;

    CP_WAIT1();
    __syncthreads();
    #pragma unroll
    for (int kc = 0; kc < 8; ++kc) {
        uint32_t a0[4], a1[4];
        ldsm4(a0, base + a_off + kc * 32);
        ldsm4(a1, base + a_off + 16 * PJW + kc * 32);
        #pragma unroll
        for (int p = 0; p < 8; ++p) {
            uint32_t bb[4];
            ldsm4(bb, base + PJ_IN + (uint32_t)p * (16 * PJW) + b_off + kc * 32);
            mma16816(&acc[p][0][0], a0, bb + 0);
            mma16816(&acc[p][0][4], a0, bb + 2);
            mma16816(&acc[p][1][0], a1, bb + 0);
            mma16816(&acc[p][1][4], a1, bb + 2);
        }
    }
    CP_WAIT0();
    __syncthreads();
    #pragma unroll
    for (int kc = 8; kc < 16; ++kc) {
        uint32_t a0[4], a1[4];
        ldsm4(a0, base + a_off + kc * 32);
        ldsm4(a1, base + a_off + 16 * PJW + kc * 32);
        #pragma unroll
        for (int p = 0; p < 8; ++p) {
            uint32_t bb[4];
            ldsm4(bb, base + PJ_IN + (uint32_t)p * (16 * PJW) + b_off + kc * 32);
            mma16816(&acc[p][0][0], a0, bb + 0);
            mma16816(&acc[p][0][4], a0, bb + 2);
            mma16816(&acc[p][1][0], a1, bb + 0);
            mma16816(&acc[p][1][4], a1, bb + 2);
        }
    }

    // fp8 store (same coordinate mapping as R12's bf16 store)
    #pragma unroll
    for (int af = 0; af < 2; ++af) {
        const int rr = r0 + wid * 32 + (l >> 2) + af * 16;
        #pragma unroll
        for (int p = 0; p < 8; ++p) {
            const int colA = p * 16 + (l & 3) * 2;
            *reinterpret_cast<unsigned short*>(&Out8[(size_t)rr * QKD + colA]) =
                packfp8x2(acc[p][af][0], acc[p][af][1]);
            *reinterpret_cast<unsigned short*>(&Out8[(size_t)(rr + 8) * QKD + colA]) =
                packfp8x2(acc[p][af][2], acc[p][af][3]);
            *reinterpret_cast<unsigned short*>(&Out8[(size_t)rr * QKD + colA + 8]) =
                packfp8x2(acc[p][af][4], acc[p][af][5]);
            *reinterpret_cast<unsigned short*>(&Out8[(size_t)(rr + 8) * QKD + colA + 8]) =
                packfp8x2(acc[p][af][6], acc[p][af][7]);
        }
    }
}

// ============================================================================
// lse: fp8 e4m3 mma S=QK^T -> per-row partial sum of exp.
// grid (32 ntiles, 8 b, MSEG=8), 256 thr (8 warps x 16 Q-rows).
// Row = 128 fp8 = 128 B; PD8=144 conflict-free. 55KB smem -> 4 CTAs/SM.
// A-fragments hoisted once; per-p fold; K double-buffered.
// ============================================================================
#define PD8 144
#define KT8 (128 * PD8)                // 18432
#define SMEM_LSE (3 * KT8)             // 55296  (x4 CTAs = 221184 < 227KB)

__global__ __launch_bounds__(256, 4)
void lse_mma_kernel() {
    extern __shared__ __align__(16) char dsm[];
    const uint32_t base = smem_u32(dsm);

    const int b   = blockIdx.y;
    const int seg = blockIdx.z;
    const int n0  = blockIdx.x * 128;
    const int tid = threadIdx.x;
    const int wid = tid >> 5;
    const int l   = tid & 31;

    const uint8_t* __restrict__ Qh = g_Qh8 + ((size_t)b * NTOK + n0) * QKD;
    const uint8_t* __restrict__ Kh = g_Kh8 + (size_t)b * NTOK * QKD;

    // prologue: Q (128 rows x 128 B) + K tile 0
    for (int idx = tid; idx < 1024; idx += 256) {
        const int r = idx >> 3, c = idx & 7;
        cp16(base + (uint32_t)r * PD8 + (uint32_t)c * 16, Qh + (size_t)r * QKD + c * 16);
        cp16(base + KT8 + (uint32_t)r * PD8 + (uint32_t)c * 16,
             Kh + ((size_t)(seg * 512 + r)) * QKD + c * 16);
    }
    CP_COMMIT();
    CP_WAIT0();
    __syncthreads();

    const uint32_t a_row = (uint32_t)(wid * 16 + (l & 7) + ((l >> 3) & 1) * 8);
    const uint32_t a_off = a_row * PD8 + ((uint32_t)(l >> 4) & 1) * 16;
    const uint32_t b_row = (uint32_t)((l & 7) + ((l >> 4) & 1) * 8);
    const uint32_t b_off = b_row * PD8 + (((uint32_t)(l >> 3)) & 1) * 16;

    // hoist A fragments (4 kc chunks of K=32 fp8 = 32 B): 16 regs
    uint32_t af[4][4];
    #pragma unroll
    for (int kc = 0; kc < 4; ++kc)
        ldsm4(af[kc], base + a_off + kc * 32);

    float rs0 = 0.f, rs1 = 0.f;

    for (int mt = 0; mt < 4; ++mt) {
        const int sb = mt & 1;
        if (mt + 1 < 4) {
            const int m0 = seg * 512 + (mt + 1) * 128;
            const uint32_t kb = base + KT8 + ((mt + 1) & 1) * KT8;
            for (int idx = tid; idx < 1024; idx += 256) {
                const int r = idx >> 3, c = idx & 7;
                cp16(kb + (uint32_t)r * PD8 + (uint32_t)c * 16,
                     Kh + ((size_t)(m0 + r)) * QKD + c * 16);
            }
            CP_COMMIT();
            CP_WAIT1();
        } else {
            CP_WAIT0();
        }
        __syncthreads();

        const uint32_t kh = base + KT8 + (uint32_t)sb * KT8;

        #pragma unroll
        for (int p = 0; p < 8; ++p) {
            float acc[8];
            #pragma unroll
            for (int i = 0; i < 8; ++i) acc[i] = 0.f;
            #pragma unroll
            for (int kc = 0; kc < 4; ++kc) {
                uint32_t bh[4];
                ldsm4(bh, kh + (uint32_t)p * (16 * PD8) + b_off + kc * 32);
                mma16832f8(acc + 0, af[kc], bh + 0);   // n0-7:  {k0-15, k16-31}
                mma16832f8(acc + 4, af[kc], bh + 2);   // n8-15
            }
            rs0 += ex2f(acc[0] * SCLOG2E) + ex2f(acc[1] * SCLOG2E)
                 + ex2f(acc[4] * SCLOG2E) + ex2f(acc[5] * SCLOG2E);
            rs1 += ex2f(acc[2] * SCLOG2E) + ex2f(acc[3] * SCLOG2E)
                 + ex2f(acc[6] * SCLOG2E) + ex2f(acc[7] * SCLOG2E);
        }
        __syncthreads();
    }

    rs0 += __shfl_xor_sync(0xFFFFFFFFu, rs0, 1);
    rs0 += __shfl_xor_sync(0xFFFFFFFFu, rs0, 2);
    rs1 += __shfl_xor_sync(0xFFFFFFFFu, rs1, 1);
    rs1 += __shfl_xor_sync(0xFFFFFFFFu, rs1, 2);
    if ((l & 3) == 0) {
        const int row = n0 + wid * 16 + (l >> 2);
        g_plse[(size_t)(b * NTOK + row) * MSEG + seg]     = rs0;
        g_plse[(size_t)(b * NTOK + row + 8) * MSEG + seg] = rs1;
    }
}

// ============================================================================
// merged: blocks 0..7 -> w_keep = s/sum(s); blocks 8..39 -> slot softmax.
// 1024 threads (latency).
// ============================================================================
__global__ __launch_bounds__(1024, 1)
void wk_slots_kernel(const float* __restrict__ slot_logits) {
    __shared__ float vals[NTOK];
    __shared__ float sred[1024];
    const int tid = threadIdx.x;

    if (blockIdx.x < BSZ) {
        const int b = blockIdx.x;
        float sv[4];
        float loc = 0.f;
        #pragma unroll
        for (int j = 0; j < 4; ++j) {
            const int n = j * 1024 + tid;
            const float* p = &g_plse[(size_t)(b * NTOK + n) * MSEG];
            float s = 0.f;
            #pragma unroll
            for (int k = 0; k < MSEG; ++k) s += p[k];
            sv[j] = s;
            loc += s;
        }
        sred[tid] = loc; __syncthreads();
        for (int st = 512; st; st >>= 1) {
            if (tid < st) sred[tid] += sred[tid + st];
            __syncthreads();
        }
        const float inv = 1.f / sred[0];
        #pragma unroll
        for (int j = 0; j < 4; ++j)
            g_wkeep[(size_t)b * NTOK + j * 1024 + tid] = sv[j] * inv;
    } else {
        const int row = blockIdx.x - BSZ;
        const float* __restrict__ x = slot_logits + (size_t)row * NTOK;
        float* __restrict__ y = g_slotw + (size_t)row * NTOK;
        float sm = 0.f;
        #pragma unroll
        for (int j = 0; j < 4; ++j) {
            const int i = j * 1024 + tid;
            const float e = ex2f(x[i] * LOG2E);
            vals[i] = e;
            sm += e;
        }
        sred[tid] = sm; __syncthreads();
        for (int s = 512; s; s >>= 1) {
            if (tid < s) sred[tid] += sred[tid + s];
            __syncthreads();
        }
        const float inv = 1.f / sred[0];
        #pragma unroll
        for (int j = 0; j < 4; ++j) {
            const int i = j * 1024 + tid;
            y[i] = vals[i] * inv;
        }
    }
}

// den[b][m] = sum_n slot_w[m][n] * w_keep[b][n]
__global__ void den_kernel() {
    const int m = blockIdx.x, b = blockIdx.y;
    __shared__ float sred[256];
    const int tid = threadIdx.x;
    const float* __restrict__ sw = g_slotw + (size_t)m * NTOK;
    const float* __restrict__ wk = g_wkeep + (size_t)b * NTOK;
    float s = 0.f;
    for (int n = tid; n < NTOK; n += 256) s = fmaf(sw[n], wk[n], s);
    sred[tid] = s; __syncthreads();
    for (int st = 128; st; st >>= 1) {
        if (tid < st) sred[tid] += sred[tid + st];
        __syncthreads();
    }
    if (tid == 0) g_den[b * MSL + m] = sred[0];
}

// ============================================================================
// partial out over n-segments, fp32 H0 (bf16 H here fails tolerance: output is
// a near-uniform average, bf16 noise does NOT wash out).
// grid (8 b, 32), 256 thr: half h = tid>>7 handles 64 n, col = tid&127.
// ============================================================================
__global__ __launch_bounds__(256, 1)
void pout_kernel(const float* __restrict__ H0) {
    const int b = blockIdx.x, sege = blockIdx.y;
    const int tid = threadIdx.x;
    const int h   = tid >> 7;         // 0/1: n-half (64 n each)
    const int col = tid & 127;        // d pair (d = 2*col)
    __shared__ float csh[MSL][128];

    const int nb = sege * 128;
    for (int i = tid; i < MSL * 128; i += 256) {
        const int m = i >> 7, nn = i & 127;
        csh[m][nn] = g_slotw[(size_t)m * NTOK + nb + nn]
                   * g_wkeep[(size_t)b * NTOK + nb + nn];
    }
    __syncthreads();

    float acc0[MSL], acc1[MSL];
    #pragma unroll
    for (int m = 0; m < MSL; ++m) { acc0[m] = 0.f; acc1[m] = 0.f; }

    const int n0 = nb + h * 64;
    for (int nn = 0; nn < 64; ++nn) {
        const float2 h2 = *reinterpret_cast<const float2*>(
            &H0[((size_t)b * NTOK + n0 + nn) * DDIM + 2 * col]);
        #pragma unroll
        for (int m = 0; m < MSL; ++m) {
            const float w = csh[m][h * 64 + nn];
            acc0[m] = fmaf(w, h2.x, acc0[m]);
            acc1[m] = fmaf(w, h2.y, acc1[m]);
        }
    }
    const int seg = sege * 2 + h;
    #pragma unroll
    for (int m = 0; m < MSL; ++m) {
        float2 v = make_float2(acc0[m], acc1[m]);
        *reinterpret_cast<float2*>(
            &g_pout[((size_t)((b * OSEG + seg) * MSL) + m) * DDIM + 2 * col]) = v;
    }
}

// out = (sum_seg partial) / (den + 1e-6)
__global__ void final_kernel(float* __restrict__ out) {
    const int idx = blockIdx.x * 256 + threadIdx.x;
    if (idx >= BSZ * MSL * DDIM) return;
    const int m = (idx >> 8) & 31;
    const int b = idx >> 13;
    float s = 0.f;
    #pragma unroll
    for (int seg = 0; seg < OSEG; ++seg)
        s += g_pout[((size_t)((b * OSEG + seg) * MSL) + m) * DDIM + (idx & 255)];
    out[idx] = s / (g_den[b * MSL + m] + 1e-6f);
}

// ============================================================================
extern "C" void kernel_launch(void* const* d_in, const int* in_sizes, int n_in,
                              void* d_out, int out_size) {
    const float* X0  = (const float*)d_in[0];
    const float* H0  = (const float*)d_in[1];
    const float* Wq  = (const float*)d_in[2];
    const float* Wk  = (const float*)d_in[3];
    const float* slo = (const float*)d_in[4];
    float* out = (float*)d_out;

    cudaFuncSetAttribute(proj_mma_kernel, cudaFuncAttributeMaxDynamicSharedMemorySize, PJ_SMEM);
    cudaFuncSetAttribute(lse_mma_kernel,  cudaFuncAttributeMaxDynamicSharedMemorySize, SMEM_LSE);

    convert_kernel<<<8192 + 128, 256>>>(X0, H0, Wq, Wk);
    proj_mma_kernel<<<dim3(128, 2), 256, PJ_SMEM>>>();
    lse_mma_kernel<<<dim3(NTOK / 128, BSZ, MSEG), 256, SMEM_LSE>>>();
    wk_slots_kernel<<<BSZ + MSL, 1024>>>(slo);
    den_kernel<<<dim3(MSL, BSZ), 256>>>();
    pout_kernel<<<dim3(BSZ, 32), 256>>>(H0);
    final_kernel<<<(BSZ * MSL * DDIM + 255) / 256, 256>>>(out);
}

// round 16
// speedup vs baseline: 1.1483x; 1.0181x over previous
#include <cuda_runtime.h>
#include <cuda_bf16.h>
#include <cuda_fp8.h>
#include <cstdint>
#include <stdint.h>
#include <math.h>

// Problem constants
#define BSZ   8
#define NTOK  4096
#define DDIM  256
#define QKD   128
#define MSL   32
#define MSEG  8      // K-token segments for the lse kernel (512 K rows each)
#define OSEG  64     // n-range segments for the output kernel (64 n each)

#define SCLOG2E (0.08838834764831845f * 1.44269504088896340f)  // scale * log2(e)
#define LOG2E   1.44269504088896340f

// ---------------- scratch (static device globals; no allocs allowed) ----------
__device__ __align__(16) uint8_t g_H8[BSZ * NTOK * DDIM];   // e4m3 inputs
__device__ __align__(16) uint8_t g_X8[BSZ * NTOK * DDIM];
__device__ __align__(16) uint8_t g_Wq8[QKD * DDIM];         // [q][d] transposed, e4m3
__device__ __align__(16) uint8_t g_Wk8[QKD * DDIM];
__device__ __align__(16) uint8_t g_Qh8[BSZ * NTOK * QKD];   // e4m3
__device__ __align__(16) uint8_t g_Kh8[BSZ * NTOK * QKD];   // e4m3
__device__ float g_plse[BSZ * NTOK * MSEG];
__device__ float g_wkeep[BSZ * NTOK];
__device__ float g_slotw[MSL * NTOK];
__device__ float g_den[BSZ * MSL];
__device__ float g_pout[BSZ * OSEG * MSL * DDIM];

// ---------------- PTX helpers (baseline sm_100) ----------------
__device__ __forceinline__ uint32_t smem_u32(const void* p) {
    uint32_t a;
    asm("{ .reg .u64 t; cvta.to.shared.u64 t, %1; cvt.u32.u64 %0, t; }" : "=r"(a) : "l"(p));
    return a;
}
__device__ __forceinline__ void cp16(uint32_t dst, const void* src) {
    asm volatile("cp.async.cg.shared.global [%0], [%1], 16;" :: "r"(dst), "l"(src) : "memory");
}
#define CP_COMMIT() asm volatile("cp.async.commit_group;" ::: "memory")
#define CP_WAIT0()  asm volatile("cp.async.wait_group 0;" ::: "memory")
#define CP_WAIT1()  asm volatile("cp.async.wait_group 1;" ::: "memory")

__device__ __forceinline__ void ldsm4(uint32_t* r, uint32_t addr) {
    asm volatile("ldmatrix.sync.aligned.m8n8.x4.shared.b16 {%0,%1,%2,%3}, [%4];"
                 : "=r"((r)[0]), "=r"((r)[1]), "=r"((r)[2]), "=r"((r)[3]) : "r"(addr));
}
// fp8 e4m3 MMA, K=32 per instruction
__device__ __forceinline__ void mma16832f8(float* c, const uint32_t* a, const uint32_t* b) {
    asm volatile(
        "mma.sync.aligned.m16n8k32.row.col.f32.e4m3.e4m3.f32 "
        "{%0,%1,%2,%3}, {%4,%5,%6,%7}, {%8,%9}, {%0,%1,%2,%3};"
        : "+f"((c)[0]), "+f"((c)[1]), "+f"((c)[2]), "+f"((c)[3])
        : "r"((a)[0]), "r"((a)[1]), "r"((a)[2]), "r"((a)[3]),
          "r"((b)[0]), "r"((b)[1]));
}
__device__ __forceinline__ float ex2f(float x) {
    float y;
    asm("ex2.approx.f32 %0, %1;" : "=f"(y) : "f"(x));
    return y;
}
__device__ __forceinline__ unsigned short packfp8x2(float a, float b) {
    return (unsigned short)__nv_cvt_float2_to_fp8x2(make_float2(a, b), __NV_SATFINITE, __NV_E4M3);
}
__device__ __forceinline__ uint32_t packfp8x4(float4 v) {
    const uint32_t lo = packfp8x2(v.x, v.y);
    const uint32_t hi = packfp8x2(v.z, v.w);
    return lo | (hi << 16);
}

// ============================================================================
// convert inputs + weights to fp8 e4m3 (merged)
// ============================================================================
__global__ void convert_kernel(const float* __restrict__ X0, const float* __restrict__ H0,
                               const float* __restrict__ Wq, const float* __restrict__ Wk) {
    if (blockIdx.x < 8192) {
        const size_t i = (size_t)blockIdx.x * 256 + threadIdx.x;   // float4 index
        float4 h = reinterpret_cast<const float4*>(H0)[i];
        float4 x = reinterpret_cast<const float4*>(X0)[i];
        reinterpret_cast<uint32_t*>(g_H8)[i] = packfp8x4(h);
        reinterpret_cast<uint32_t*>(g_X8)[i] = packfp8x4(x);
    } else {
        const int i = (blockIdx.x - 8192) * 256 + threadIdx.x;  // over QKD*DDIM
        const int q = i >> 8, d = i & 255;
        __nv_fp8_e4m3 vq(Wq[d * QKD + q]);
        __nv_fp8_e4m3 vk(Wk[d * QKD + q]);
        g_Wq8[i] = *reinterpret_cast<uint8_t*>(&vq);
        g_Wk8[i] = *reinterpret_cast<uint8_t*>(&vk);
    }
}

// ============================================================================
// proj via fp8 mma: Q = H8 @ Wq8^T, K = X8 @ Wk8^T.  M=128/block, N=128, K=256.
// grid (256 rowtiles, 2), 256 thr (8 warps x 16 rows). Rows 256 B, pad 272 B.
// 69.6 KB smem -> 2 CTAs/SM.
// ============================================================================
#define P8W 272
#define P8_IN   (128 * P8W)            // 34816
#define P8_SMEM (2 * P8_IN)            // 69632

__global__ __launch_bounds__(256, 2)
void proj_mma_kernel() {
    extern __shared__ __align__(16) char dsm[];
    const uint32_t base = smem_u32(dsm);
    const int which = blockIdx.y;
    const uint8_t* __restrict__ In = which ? g_X8 : g_H8;
    const uint8_t* __restrict__ Wt = which ? g_Wk8 : g_Wq8;
    uint8_t* __restrict__ Out8 = which ? g_Kh8 : g_Qh8;

    const int r0  = blockIdx.x * 128;
    const int tid = threadIdx.x;
    const int wid = tid >> 5;
    const int l   = tid & 31;

    // load In tile (128 rows x 256 B) + Wt (128 rows x 256 B)
    for (int idx = tid; idx < 2048; idx += 256) {
        const int r = idx >> 4, c = idx & 15;
        cp16(base + (uint32_t)r * P8W + (uint32_t)c * 16,
             In + (size_t)(r0 + r) * DDIM + c * 16);
        cp16(base + P8_IN + (uint32_t)r * P8W + (uint32_t)c * 16,
             Wt + (size_t)r * DDIM + c * 16);
    }
    CP_COMMIT(); CP_WAIT0();
    __syncthreads();

    const uint32_t a_row = (uint32_t)(wid * 16 + (l & 7) + ((l >> 3) & 1) * 8);
    const uint32_t a_off = a_row * P8W + ((uint32_t)(l >> 4) & 1) * 16;
    const uint32_t b_row = (uint32_t)((l & 7) + ((l >> 4) & 1) * 8);
    const uint32_t b_off = b_row * P8W + (((uint32_t)(l >> 3)) & 1) * 16;

    float acc[64];
    #pragma unroll
    for (int i = 0; i < 64; ++i) acc[i] = 0.f;

    #pragma unroll
    for (int kc = 0; kc < 8; ++kc) {          // K=256 in 8 chunks of 32
        uint32_t a[4];
        ldsm4(a, base + a_off + kc * 32);
        #pragma unroll
        for (int p = 0; p < 8; ++p) {
            uint32_t bb[4];
            ldsm4(bb, base + P8_IN + (uint32_t)p * (16 * P8W) + b_off + kc * 32);
            mma16832f8(acc + (2 * p) * 4,     a, bb + 0);
            mma16832f8(acc + (2 * p + 1) * 4, a, bb + 2);
        }
    }

    // fp8 store (R9-validated C mapping): group g covers cols g*8..+7
    const int rr = r0 + wid * 16 + (l >> 2);
    #pragma unroll
    for (int g = 0; g < 16; ++g) {
        const int col = g * 8 + (l & 3) * 2;
        *reinterpret_cast<unsigned short*>(&Out8[(size_t)rr * QKD + col]) =
            packfp8x2(acc[g * 4 + 0], acc[g * 4 + 1]);
        *reinterpret_cast<unsigned short*>(&Out8[(size_t)(rr + 8) * QKD + col]) =
            packfp8x2(acc[g * 4 + 2], acc[g * 4 + 3]);
    }
}

// ============================================================================
// lse: fp8 e4m3 mma S=QK^T -> per-row partial sum of exp.  (R15, unchanged)
// grid (32 ntiles, 8 b, MSEG=8), 256 thr (8 warps x 16 Q-rows). 4 CTAs/SM.
// ============================================================================
#define PD8 144
#define KT8 (128 * PD8)                // 18432
#define SMEM_LSE (3 * KT8)             // 55296

__global__ __launch_bounds__(256, 4)
void lse_mma_kernel() {
    extern __shared__ __align__(16) char dsm[];
    const uint32_t base = smem_u32(dsm);

    const int b   = blockIdx.y;
    const int seg = blockIdx.z;
    const int n0  = blockIdx.x * 128;
    const int tid = threadIdx.x;
    const int wid = tid >> 5;
    const int l   = tid & 31;

    const uint8_t* __restrict__ Qh = g_Qh8 + ((size_t)b * NTOK + n0) * QKD;
    const uint8_t* __restrict__ Kh = g_Kh8 + (size_t)b * NTOK * QKD;

    for (int idx = tid; idx < 1024; idx += 256) {
        const int r = idx >> 3, c = idx & 7;
        cp16(base + (uint32_t)r * PD8 + (uint32_t)c * 16, Qh + (size_t)r * QKD + c * 16);
        cp16(base + KT8 + (uint32_t)r * PD8 + (uint32_t)c * 16,
             Kh + ((size_t)(seg * 512 + r)) * QKD + c * 16);
    }
    CP_COMMIT();
    CP_WAIT0();
    __syncthreads();

    const uint32_t a_row = (uint32_t)(wid * 16 + (l & 7) + ((l >> 3) & 1) * 8);
    const uint32_t a_off = a_row * PD8 + ((uint32_t)(l >> 4) & 1) * 16;
    const uint32_t b_row = (uint32_t)((l & 7) + ((l >> 4) & 1) * 8);
    const uint32_t b_off = b_row * PD8 + (((uint32_t)(l >> 3)) & 1) * 16;

    uint32_t af[4][4];
    #pragma unroll
    for (int kc = 0; kc < 4; ++kc)
        ldsm4(af[kc], base + a_off + kc * 32);

    float rs0 = 0.f, rs1 = 0.f;

    for (int mt = 0; mt < 4; ++mt) {
        const int sb = mt & 1;
        if (mt + 1 < 4) {
            const int m0 = seg * 512 + (mt + 1) * 128;
            const uint32_t kb = base + KT8 + ((mt + 1) & 1) * KT8;
            for (int idx = tid; idx < 1024; idx += 256) {
                const int r = idx >> 3, c = idx & 7;
                cp16(kb + (uint32_t)r * PD8 + (uint32_t)c * 16,
                     Kh + ((size_t)(m0 + r)) * QKD + c * 16);
            }
            CP_COMMIT();
            CP_WAIT1();
        } else {
            CP_WAIT0();
        }
        __syncthreads();

        const uint32_t kh = base + KT8 + (uint32_t)sb * KT8;

        #pragma unroll
        for (int p = 0; p < 8; ++p) {
            float acc[8];
            #pragma unroll
            for (int i = 0; i < 8; ++i) acc[i] = 0.f;
            #pragma unroll
            for (int kc = 0; kc < 4; ++kc) {
                uint32_t bh[4];
                ldsm4(bh, kh + (uint32_t)p * (16 * PD8) + b_off + kc * 32);
                mma16832f8(acc + 0, af[kc], bh + 0);
                mma16832f8(acc + 4, af[kc], bh + 2);
            }
            rs0 += ex2f(acc[0] * SCLOG2E) + ex2f(acc[1] * SCLOG2E)
                 + ex2f(acc[4] * SCLOG2E) + ex2f(acc[5] * SCLOG2E);
            rs1 += ex2f(acc[2] * SCLOG2E) + ex2f(acc[3] * SCLOG2E)
                 + ex2f(acc[6] * SCLOG2E) + ex2f(acc[7] * SCLOG2E);
        }
        __syncthreads();
    }

    rs0 += __shfl_xor_sync(0xFFFFFFFFu, rs0, 1);
    rs0 += __shfl_xor_sync(0xFFFFFFFFu, rs0, 2);
    rs1 += __shfl_xor_sync(0xFFFFFFFFu, rs1, 1);
    rs1 += __shfl_xor_sync(0xFFFFFFFFu, rs1, 2);
    if ((l & 3) == 0) {
        const int row = n0 + wid * 16 + (l >> 2);
        g_plse[(size_t)(b * NTOK + row) * MSEG + seg]     = rs0;
        g_plse[(size_t)(b * NTOK + row + 8) * MSEG + seg] = rs1;
    }
}

// ============================================================================
// merged: blocks 0..7 -> w_keep = s/sum(s); blocks 8..39 -> slot softmax.
// ============================================================================
__global__ __launch_bounds__(1024, 1)
void wk_slots_kernel(const float* __restrict__ slot_logits) {
    __shared__ float vals[NTOK];
    __shared__ float sred[1024];
    const int tid = threadIdx.x;

    if (blockIdx.x < BSZ) {
        const int b = blockIdx.x;
        float sv[4];
        float loc = 0.f;
        #pragma unroll
        for (int j = 0; j < 4; ++j) {
            const int n = j * 1024 + tid;
            const float* p = &g_plse[(size_t)(b * NTOK + n) * MSEG];
            float s = 0.f;
            #pragma unroll
            for (int k = 0; k < MSEG; ++k) s += p[k];
            sv[j] = s;
            loc += s;
        }
        sred[tid] = loc; __syncthreads();
        for (int st = 512; st; st >>= 1) {
            if (tid < st) sred[tid] += sred[tid + st];
            __syncthreads();
        }
        const float inv = 1.f / sred[0];
        #pragma unroll
        for (int j = 0; j < 4; ++j)
            g_wkeep[(size_t)b * NTOK + j * 1024 + tid] = sv[j] * inv;
    } else {
        const int row = blockIdx.x - BSZ;
        const float* __restrict__ x = slot_logits + (size_t)row * NTOK;
        float* __restrict__ y = g_slotw + (size_t)row * NTOK;
        float sm = 0.f;
        #pragma unroll
        for (int j = 0; j < 4; ++j) {
            const int i = j * 1024 + tid;
            const float e = ex2f(x[i] * LOG2E);
            vals[i] = e;
            sm += e;
        }
        sred[tid] = sm; __syncthreads();
        for (int s = 512; s; s >>= 1) {
            if (tid < s) sred[tid] += sred[tid + s];
            __syncthreads();
        }
        const float inv = 1.f / sred[0];
        #pragma unroll
        for (int j = 0; j < 4; ++j) {
            const int i = j * 1024 + tid;
            y[i] = vals[i] * inv;
        }
    }
}

// den[b][m] = sum_n slot_w[m][n] * w_keep[b][n]
__global__ void den_kernel() {
    const int m = blockIdx.x, b = blockIdx.y;
    __shared__ float sred[256];
    const int tid = threadIdx.x;
    const float* __restrict__ sw = g_slotw + (size_t)m * NTOK;
    const float* __restrict__ wk = g_wkeep + (size_t)b * NTOK;
    float s = 0.f;
    for (int n = tid; n < NTOK; n += 256) s = fmaf(sw[n], wk[n], s);
    sred[tid] = s; __syncthreads();
    for (int st = 128; st; st >>= 1) {
        if (tid < st) sred[tid] += sred[tid + st];
        __syncthreads();
    }
    if (tid == 0) g_den[b * MSL + m] = sred[0];
}

// ============================================================================
// partial out over n-segments, fp32 H0 (bf16/fp8 H here fails tolerance —
// output is a near-uniform average; low-precision noise does NOT wash out).
// grid (8 b, 32), 256 thr: half h = tid>>7 handles 64 n, col = tid&127.
// ============================================================================
__global__ __launch_bounds__(256, 1)
void pout_kernel(const float* __restrict__ H0) {
    const int b = blockIdx.x, sege = blockIdx.y;
    const int tid = threadIdx.x;
    const int h   = tid >> 7;         // 0/1: n-half (64 n each)
    const int col = tid & 127;        // d pair (d = 2*col)
    __shared__ float csh[MSL][128];

    const int nb = sege * 128;
    for (int i = tid; i < MSL * 128; i += 256) {
        const int m = i >> 7, nn = i & 127;
        csh[m][nn] = g_slotw[(size_t)m * NTOK + nb + nn]
                   * g_wkeep[(size_t)b * NTOK + nb + nn];
    }
    __syncthreads();

    float acc0[MSL], acc1[MSL];
    #pragma unroll
    for (int m = 0; m < MSL; ++m) { acc0[m] = 0.f; acc1[m] = 0.f; }

    const int n0 = nb + h * 64;
    for (int nn = 0; nn < 64; ++nn) {
        const float2 h2 = *reinterpret_cast<const float2*>(
            &H0[((size_t)b * NTOK + n0 + nn) * DDIM + 2 * col]);
        #pragma unroll
        for (int m = 0; m < MSL; ++m) {
            const float w = csh[m][h * 64 + nn];
            acc0[m] = fmaf(w, h2.x, acc0[m]);
            acc1[m] = fmaf(w, h2.y, acc1[m]);
        }
    }
    const int seg = sege * 2 + h;
    #pragma unroll
    for (int m = 0; m < MSL; ++m) {
        float2 v = make_float2(acc0[m], acc1[m]);
        *reinterpret_cast<float2*>(
            &g_pout[((size_t)((b * OSEG + seg) * MSL) + m) * DDIM + 2 * col]) = v;
    }
}

// out = (sum_seg partial) / (den + 1e-6)
__global__ void final_kernel(float* __restrict__ out) {
    const int idx = blockIdx.x * 256 + threadIdx.x;
    if (idx >= BSZ * MSL * DDIM) return;
    const int m = (idx >> 8) & 31;
    const int b = idx >> 13;
    float s = 0.f;
    #pragma unroll
    for (int seg = 0; seg < OSEG; ++seg)
        s += g_pout[((size_t)((b * OSEG + seg) * MSL) + m) * DDIM + (idx & 255)];
    out[idx] = s / (g_den[b * MSL + m] + 1e-6f);
}

// ============================================================================
extern "C" void kernel_launch(void* const* d_in, const int* in_sizes, int n_in,
                              void* d_out, int out_size) {
    const float* X0  = (const float*)d_in[0];
    const float* H0  = (const float*)d_in[1];
    const float* Wq  = (const float*)d_in[2];
    const float* Wk  = (const float*)d_in[3];
    const float* slo = (const float*)d_in[4];
    float* out = (float*)d_out;

    cudaFuncSetAttribute(proj_mma_kernel, cudaFuncAttributeMaxDynamicSharedMemorySize, P8_SMEM);
    cudaFuncSetAttribute(lse_mma_kernel,  cudaFuncAttributeMaxDynamicSharedMemorySize, SMEM_LSE);

    convert_kernel<<<8192 + 128, 256>>>(X0, H0, Wq, Wk);
    proj_mma_kernel<<<dim3(256, 2), 256, P8_SMEM>>>();
    lse_mma_kernel<<<dim3(NTOK / 128, BSZ, MSEG), 256, SMEM_LSE>>>();
    wk_slots_kernel<<<BSZ + MSL, 1024>>>(slo);
    den_kernel<<<dim3(MSL, BSZ), 256>>>();
    pout_kernel<<<dim3(BSZ, 32), 256>>>(H0);
    final_kernel<<<(BSZ * MSL * DDIM + 255) / 256, 256>>>(out);
}